// round 8
// baseline (speedup 1.0000x reference)
#include <cuda_runtime.h>
#include <cmath>

#define NLEVELS 16
#define TBL 524288u
#define BLOCK 256
#define MAXP  262144
#define NBINS 32768          /* 32^3 spatial bins */

struct LevelParams {
    float    scale[NLEVELS];
    unsigned res[NLEVELS];
    unsigned off[NLEVELS];
    int      fhl;
};

/* ---- sort scratch (device globals; no allocation) ---- */
__device__ unsigned g_hist[NBINS];
__device__ unsigned g_off[NBINS];
__device__ int      g_perm[MAXP];
__device__ float    g_pos_sorted[MAXP * 3];

__device__ __forceinline__ unsigned bin_of(float x, float y, float z)
{
    unsigned ix = (unsigned)(x * 32.0f); ix = ix > 31u ? 31u : ix;
    unsigned iy = (unsigned)(y * 32.0f); iy = iy > 31u ? 31u : iy;
    unsigned iz = (unsigned)(z * 32.0f); iz = iz > 31u ? 31u : iz;
    return ix | (iy << 5) | (iz << 10);
}

__global__ void zero_hist_kernel()
{
    int i = blockIdx.x * blockDim.x + threadIdx.x;
    if (i < NBINS) g_hist[i] = 0u;
}

__global__ void hist_kernel(const float* __restrict__ pos, int n)
{
    int i = blockIdx.x * blockDim.x + threadIdx.x;
    if (i < n) {
        unsigned b = bin_of(pos[i * 3], pos[i * 3 + 1], pos[i * 3 + 2]);
        atomicAdd(&g_hist[b], 1u);
    }
}

/* one block, 1024 threads, 32 bins each: exclusive prefix sum of g_hist -> g_off */
__global__ __launch_bounds__(1024)
void scan_kernel()
{
    __shared__ unsigned s_sum[1024];
    const int t = threadIdx.x;
    unsigned local[32];
    unsigned sum = 0;
#pragma unroll
    for (int i = 0; i < 32; ++i) { local[i] = g_hist[t * 32 + i]; sum += local[i]; }
    s_sum[t] = sum;
    __syncthreads();
    for (int off = 1; off < 1024; off <<= 1) {
        unsigned v = (t >= off) ? s_sum[t - off] : 0u;
        __syncthreads();
        s_sum[t] += v;
        __syncthreads();
    }
    unsigned running = s_sum[t] - sum;   /* exclusive base for this chunk */
#pragma unroll
    for (int i = 0; i < 32; ++i) { g_off[t * 32 + i] = running; running += local[i]; }
}

__global__ void scatter_kernel(const float* __restrict__ pos, int n)
{
    int i = blockIdx.x * blockDim.x + threadIdx.x;
    if (i < n) {
        const float x = pos[i * 3], y = pos[i * 3 + 1], z = pos[i * 3 + 2];
        unsigned b = bin_of(x, y, z);
        unsigned dst = atomicAdd(&g_off[b], 1u);
        g_perm[dst] = i;
        g_pos_sorted[dst * 3 + 0] = x;
        g_pos_sorted[dst * 3 + 1] = y;
        g_pos_sorted[dst * 3 + 2] = z;
    }
}

/* ---- main encoder (R5 structure: depth-2 pipeline + pair merge) ---- */

__device__ __forceinline__ void calc_level(const LevelParams& lp, int l,
                                           float px, float py, float pz,
                                           unsigned idx[8],
                                           float& rx, float& ry, float& rz)
{
    const float s = lp.scale[l];
    const float sx = __fadd_rn(__fmul_rn(px, s), 0.5f);
    const float sy = __fadd_rn(__fmul_rn(py, s), 0.5f);
    const float sz = __fadd_rn(__fmul_rn(pz, s), 0.5f);
    const float fx = floorf(sx), fy = floorf(sy), fz = floorf(sz);
    rx = sx - fx; ry = sy - fy; rz = sz - fz;
    const unsigned x0 = (unsigned)fx;
    const unsigned y0 = (unsigned)fy;
    const unsigned z0 = (unsigned)fz;
    const unsigned off = lp.off[l];

    if (l < lp.fhl) {
        const unsigned r  = lp.res[l];
        const unsigned r2 = r * r;
        const unsigned base = off + x0 + y0 * r + z0 * r2;
        idx[0] = base;           idx[1] = base + r2;
        idx[2] = base + r;       idx[3] = base + r + r2;
        idx[4] = base + 1u;      idx[5] = base + 1u + r2;
        idx[6] = base + 1u + r;  idx[7] = base + 1u + r + r2;
    } else {
        const unsigned hy0 = y0 * 2654435761u;
        const unsigned hy1 = hy0 + 2654435761u;
        const unsigned hz0 = z0 * 805459861u;
        const unsigned hz1 = hz0 + 805459861u;
        const unsigned m = TBL - 1u;
        const unsigned x1 = x0 + 1u;
        idx[0] = off + ((x0 ^ hy0 ^ hz0) & m);
        idx[1] = off + ((x0 ^ hy0 ^ hz1) & m);
        idx[2] = off + ((x0 ^ hy1 ^ hz0) & m);
        idx[3] = off + ((x0 ^ hy1 ^ hz1) & m);
        idx[4] = off + ((x1 ^ hy0 ^ hz0) & m);
        idx[5] = off + ((x1 ^ hy0 ^ hz1) & m);
        idx[6] = off + ((x1 ^ hy1 ^ hz0) & m);
        idx[7] = off + ((x1 ^ hy1 ^ hz1) & m);
    }
}

__device__ __forceinline__ void load_level(const float2* __restrict__ lat,
                                           const unsigned idx[8], float2 v[8])
{
#pragma unroll
    for (int k = 0; k < 4; ++k) {
        const unsigned a = idx[k];
        const unsigned b = idx[k + 4];
        if ((a ^ b) == 1u) {
            const float4 q = __ldg(reinterpret_cast<const float4*>(lat) + (a >> 1));
            const float2 lo = make_float2(q.x, q.y);
            const float2 hi = make_float2(q.z, q.w);
            if (a & 1u) { v[k] = hi; v[k + 4] = lo; }
            else        { v[k] = lo; v[k + 4] = hi; }
        } else {
            v[k]     = __ldg(lat + a);
            v[k + 4] = __ldg(lat + b);
        }
    }
}

__global__ __launch_bounds__(BLOCK, 3)
void hashgrid_enc_kernel(const float* __restrict__ pos_src,
                         const float* __restrict__ latents,
                         float* __restrict__ out,
                         int n_points, LevelParams lp, int use_perm)
{
    __shared__ float s_out[32 * 257];
    __shared__ int   s_perm[BLOCK];

    const int tid = threadIdx.x;
    const int p   = blockIdx.x * BLOCK + tid;
    const int pc  = (p < n_points) ? p : (n_points > 0 ? n_points - 1 : 0);

    /* original point index this thread's output belongs to */
    int orig = pc;
    const float* psrc = pos_src;
    if (use_perm) { orig = g_perm[pc]; psrc = g_pos_sorted; }
    s_perm[tid] = (p < n_points) ? orig : -1;

    const float px = psrc[pc * 3 + 0];
    const float py = psrc[pc * 3 + 1];
    const float pz = psrc[pc * 3 + 2];

    const float2* __restrict__ lat = (const float2*)latents;

    float2 v[2][8];
    float  fr[2][3];

    {
        unsigned idx[8];
        calc_level(lp, 0, px, py, pz, idx, fr[0][0], fr[0][1], fr[0][2]);
        load_level(lat, idx, v[0]);
    }

#pragma unroll
    for (int l = 0; l < NLEVELS; ++l) {
        const int cur = l & 1;
        const int nxt = cur ^ 1;
        if (l + 1 < NLEVELS) {
            unsigned idx[8];
            calc_level(lp, l + 1, px, py, pz, idx, fr[nxt][0], fr[nxt][1], fr[nxt][2]);
            load_level(lat, idx, v[nxt]);
        }

        const float rx = fr[cur][0], ry = fr[cur][1], rz = fr[cur][2];
        const float wx0 = 1.0f - rx, wx1 = rx;
        const float wy0 = 1.0f - ry, wy1 = ry;
        const float wz0 = 1.0f - rz, wz1 = rz;
        const float w00 = wx0 * wy0, w01 = wx0 * wy1;
        const float w10 = wx1 * wy0, w11 = wx1 * wy1;
        const float w0 = w00 * wz0, w1 = w00 * wz1;
        const float w2 = w01 * wz0, w3 = w01 * wz1;
        const float w4 = w10 * wz0, w5 = w10 * wz1;
        const float w6 = w11 * wz0, w7 = w11 * wz1;

        const float2* vv = v[cur];
        float a = w0 * vv[0].x + w1 * vv[1].x + w2 * vv[2].x + w3 * vv[3].x
                + w4 * vv[4].x + w5 * vv[5].x + w6 * vv[6].x + w7 * vv[7].x;
        float b = w0 * vv[0].y + w1 * vv[1].y + w2 * vv[2].y + w3 * vv[3].y
                + w4 * vv[4].y + w5 * vv[5].y + w6 * vv[6].y + w7 * vv[7].y;

        s_out[(2 * l + 0) * 257 + tid] = a;
        s_out[(2 * l + 1) * 257 + tid] = b;
    }

    __syncthreads();

    /* store: per-point 128B chunk goes to the ORIGINAL point slot. A warp covers
       4 points x 8 float4 dense -> 4 full lines per iteration, same as sequential. */
#pragma unroll
    for (int i = 0; i < 8; ++i) {
        const int g4 = i * BLOCK + tid;
        const int g  = g4 * 4;
        const int pl = g >> 5;             /* point-in-block */
        const int c  = g & 31;             /* feature column */
        const int o  = s_perm[pl];
        float4 vs;
        vs.x = s_out[(c + 0) * 257 + pl];
        vs.y = s_out[(c + 1) * 257 + pl];
        vs.z = s_out[(c + 2) * 257 + pl];
        vs.w = s_out[(c + 3) * 257 + pl];
        if (o >= 0)
            *reinterpret_cast<float4*>(out + o * 32 + c) = vs;
    }
}

static void fill_level_params(LevelParams& lp)
{
    const double b = exp((log(2048.0) - log(16.0)) / 15.0);
    unsigned off = 0;
    int fhl = 0;
    for (int i = 0; i < NLEVELS; ++i) {
        const double scale = 16.0 * pow(b, (double)i) - 1.0;
        lp.scale[i] = (float)scale;
        const unsigned res = (unsigned)ceil(scale) + 1u;
        lp.res[i] = res;
        unsigned long long n = (unsigned long long)res * res * res;
        lp.off[i] = off;
        if (n <= (unsigned long long)TBL) { fhl += 1; off += (unsigned)n; }
        else                              { off += TBL; }
    }
    lp.fhl = fhl;
}

extern "C" void kernel_launch(void* const* d_in, const int* in_sizes, int n_in,
                              void* d_out, int out_size)
{
    const float* pos     = (const float*)d_in[0];
    const float* latents = (const float*)d_in[1];
    float*       out     = (float*)d_out;

    const int n_points = in_sizes[0] / 3;

    LevelParams lp;
    fill_level_params(lp);

    const int blocks = (n_points + BLOCK - 1) / BLOCK;

    if (n_points <= MAXP) {
        zero_hist_kernel<<<(NBINS + 255) / 256, 256>>>();
        hist_kernel<<<(n_points + 255) / 256, 256>>>(pos, n_points);
        scan_kernel<<<1, 1024>>>();
        scatter_kernel<<<(n_points + 255) / 256, 256>>>(pos, n_points);
        hashgrid_enc_kernel<<<blocks, BLOCK>>>(pos, latents, out, n_points, lp, 1);
    } else {
        hashgrid_enc_kernel<<<blocks, BLOCK>>>(pos, latents, out, n_points, lp, 0);
    }
}